// round 6
// baseline (speedup 1.0000x reference)
#include <cuda_runtime.h>
#include <math.h>

#define BB 8
#define NBOX 300
#define RSEL 36
#define CCH 256
#define NROI (BB * RSEL)
#define IOU_THRS 0.7f
#define CONF_THRS 0.3f
#define GRIDP 14     // OUT*SR
#define NWORDS 10    // ceil(300/32)
#define MAXROWS 28   // 14 samples x 2 taps
#define MAXSPAN 64
#define SELTHR 640

// ---- per-ROI pooling plan (device scratch; no allocs) ----
__device__ float g_wx[NROI][MAXSPAN];
__device__ int   g_rows[NROI][MAXROWS];
__device__ float g_rwt[NROI][MAXROWS];
__device__ int4  g_meta[NROI];        // {Kr, xmin, xmax, lv}

__device__ __forceinline__ float neg_inf() { return __int_as_float(0xff800000); }

// ---------------------------------------------------------------------------
// Kernel 1 (fused): sort + IOU bitmask + serial NMS + partition + ROI prep
// One block per batch, 640 threads, everything in shared.
// ---------------------------------------------------------------------------
__global__ void __launch_bounds__(SELTHR)
select_kernel(const float* __restrict__ boxes,
              const float* __restrict__ scores)
{
    const int b   = blockIdx.x;
    const int tid = threadIdx.x;

    __shared__ float         s[NBOX];
    __shared__ float4        bx[NBOX];
    __shared__ unsigned char val[NBOX];
    __shared__ unsigned int  sup[NWORDS * NBOX];   // [t*NBOX + i]
    __shared__ unsigned int  keepW[NWORDS];
    __shared__ float4 sselBox[RSEL];
    __shared__ int    sselLv[RSEL];
    __shared__ int    sselValid[RSEL];

    // ---- scores ----
    if (tid < NBOX) {
        float sc = scores[b * NBOX + tid];
        s[tid] = (sc > CONF_THRS) ? sc : neg_inf();
    }
    __syncthreads();

    // ---- stable descending rank -> sorted boxes in shared ----
    if (tid < NBOX) {
        const float mys = s[tid];
        int rank = 0;
        #pragma unroll 4
        for (int k = 0; k < NBOX; k++) {
            float sk = s[k];
            rank += (sk > mys) || (sk == mys && k < tid);
        }
        const float* bp = boxes + (size_t)(b * NBOX + tid) * 4;
        bx[rank]  = make_float4(bp[0], bp[1], bp[2], bp[3]);
        val[rank] = (mys > CONF_THRS) ? 1 : 0;
    }
    __syncthreads();

    // ---- suppression words: flat (t, i) pairs across all 640 threads ----
    for (int p = tid; p < NWORDS * NBOX; p += SELTHR) {
        const int t = p / NBOX;
        const int i = p - t * NBOX;
        const int j0 = t * 32;
        unsigned int w = 0;
        // word is structurally zero unless some j in [j0, j0+32) has j > i
        if (i < j0 + 31) {
            const float4 a = bx[i];
            const float areaA = __fmul_rn(__fsub_rn(a.z, a.x), __fsub_rn(a.w, a.y));
            #pragma unroll 4
            for (int jj = 0; jj < 32; jj++) {
                const int j = j0 + jj;
                if (j > i && j < NBOX) {
                    float4 bb = bx[j];
                    float areaB = __fmul_rn(__fsub_rn(bb.z, bb.x), __fsub_rn(bb.w, bb.y));
                    float ltx = fmaxf(a.x, bb.x), lty = fmaxf(a.y, bb.y);
                    float rbx = fminf(a.z, bb.z), rby = fminf(a.w, bb.w);
                    float iw = fmaxf(__fsub_rn(rbx, ltx), 0.0f);
                    float ih = fmaxf(__fsub_rn(rby, lty), 0.0f);
                    float inter = __fmul_rn(iw, ih);
                    float den = __fadd_rn(__fsub_rn(__fadd_rn(areaA, areaB), inter), 1e-9f);
                    float iou = __fdiv_rn(inter, den);
                    if (iou > IOU_THRS) w |= (1u << jj);
                }
            }
        }
        sup[p] = w;
    }

    // ---- initial keep bits ----
    if (tid < NWORDS) {
        unsigned int w = 0;
        for (int jj = 0; jj < 32; jj++) {
            int j = tid * 32 + jj;
            if (j < NBOX && val[j]) w |= (1u << jj);
        }
        keepW[tid] = w;
    }
    __syncthreads();

    // ---- serial greedy pass: keep bits live in one thread's registers ----
    if (tid == 0) {
        unsigned int kw[NWORDS];
        #pragma unroll
        for (int t = 0; t < NWORDS; t++) kw[t] = keepW[t];
        for (int i = 0; i < NBOX; i++) {
            if ((kw[i >> 5] >> (i & 31)) & 1u) {
                #pragma unroll
                for (int t = 0; t < NWORDS; t++)
                    kw[t] &= ~sup[t * NBOX + i];
            }
        }
        #pragma unroll
        for (int t = 0; t < NWORDS; t++) keepW[t] = kw[t];
    }
    __syncthreads();

    // ---- stable partition select ----
    if (tid < NBOX) {
        const int w = tid >> 5, bit = tid & 31;
        int kept_before = 0;
        for (int t = 0; t < w; t++) kept_before += __popc(keepW[t]);
        kept_before += __popc(keepW[w] & ((1u << bit) - 1u));
        const bool mykeep = (keepW[w] >> bit) & 1u;
        int totKept = 0;
        for (int t = 0; t < NWORDS; t++) totKept += __popc(keepW[t]);

        int pos = mykeep ? kept_before : (totKept + (tid - kept_before));
        if (pos < RSEL) {
            float4 bb = bx[tid];
            sselBox[pos]   = bb;
            sselValid[pos] = mykeep ? 1 : 0;
            float dx = __fsub_rn(bb.z, bb.x), dy = __fsub_rn(bb.w, bb.y);
            float ss = __fadd_rn(__fmul_rn(dx, dx), __fmul_rn(dy, dy));
            float size = sqrtf(fmaxf(ss, 1e-12f));
            float t = floorf(__fadd_rn(4.0f, log2f(__fmul_rn(__fdiv_rn(size, 224.0f), 4.0f))));
            t = fminf(fmaxf(t, 2.0f), 5.0f);
            sselLv[pos] = (int)t - 2;
        }
    }
    __syncthreads();

    // ---- fused per-ROI pooling plan (threads 0..RSEL-1) ----
    if (tid < RSEL) {
        const int r   = tid;
        const int roi = b * RSEL + r;

        float wx[MAXSPAN];
        #pragma unroll
        for (int i = 0; i < MAXSPAN; i++) wx[i] = 0.0f;

        int Kr = 0, xmin = 0, xmax = -1;
        const int lv = sselLv[r];
        int   rows[MAXROWS];
        float rwt[MAXROWS];

        if (sselValid[r]) {
            const int Hs[4] = {200, 100, 50, 25};
            const int H = Hs[lv], W = H;
            const float4 bb = sselBox[r];
            const float rw = fmaxf(__fsub_rn(bb.z, bb.x), 1.0f);
            const float rh = fmaxf(__fsub_rn(bb.w, bb.y), 1.0f);

            int xm = 0x7fffffff, xM = -1;
            int ix0s[GRIDP], ix1s[GRIDP];
            float lxs[GRIDP], mxs[GRIDP];
            for (int k = 0; k < GRIDP; k++) {
                float g = (k + 0.5f) / (float)GRIDP;
                float X = __fadd_rn(bb.x, __fmul_rn(rw, g));
                float mx = (X < -1.0f || X > (float)W) ? 0.0f : 1.0f;
                float x = fminf(fmaxf(X, 0.0f), (float)(W - 1));
                int i0 = (int)floorf(x);
                int i1 = min(i0 + 1, W - 1);
                ix0s[k] = i0; ix1s[k] = i1;
                lxs[k] = __fsub_rn(x, (float)i0); mxs[k] = mx;
                if (mx > 0.0f) { if (i0 < xm) xm = i0; if (i1 > xM) xM = i1; }
            }
            if (xM >= xm && (xM - xm) < MAXSPAN) {
                for (int k = 0; k < GRIDP; k++) {
                    if (mxs[k] == 0.0f) continue;
                    wx[ix0s[k] - xm] += __fmul_rn(1.0f - lxs[k], mxs[k]);
                    wx[ix1s[k] - xm] += __fmul_rn(lxs[k], mxs[k]);
                }
                xmin = xm; xmax = xM;

                for (int k = 0; k < GRIDP; k++) {
                    float g = (k + 0.5f) / (float)GRIDP;
                    float Y = __fadd_rn(bb.y, __fmul_rn(rh, g));
                    float my = (Y < -1.0f || Y > (float)H) ? 0.0f : 1.0f;
                    float y = fminf(fmaxf(Y, 0.0f), (float)(H - 1));
                    int iy0 = (int)floorf(y);
                    int iy1 = min(iy0 + 1, H - 1);
                    float ly = __fsub_rn(y, (float)iy0);
                    float w0 = __fmul_rn(1.0f - ly, my);
                    float w1 = __fmul_rn(ly, my);
                    for (int tt = 0; tt < 2; tt++) {
                        int   row = tt ? iy1 : iy0;
                        float wv  = tt ? w1 : w0;
                        if (wv == 0.0f) continue;
                        int found = -1;
                        for (int q = 0; q < Kr; q++)
                            if (rows[q] == row) { found = q; break; }
                        if (found >= 0) rwt[found] += wv;
                        else if (Kr < MAXROWS) { rows[Kr] = row; rwt[Kr] = wv; Kr++; }
                    }
                }
            }
        }

        for (int i = 0; i < MAXSPAN; i++) g_wx[roi][i] = wx[i];
        for (int i = 0; i < MAXROWS; i++) {
            g_rows[roi][i] = (i < Kr) ? rows[i] : 0;
            g_rwt[roi][i]  = (i < Kr) ? rwt[i]  : 0.0f;
        }
        g_meta[roi] = make_int4(Kr, xmin, xmax, lv);
    }
}

// ---------------------------------------------------------------------------
// Kernel 2: pooling. One warp per (roi, 4 channels). grid (RSEL, BB, 8).
// ---------------------------------------------------------------------------
__global__ void __launch_bounds__(256)
pool_kernel(const float* __restrict__ f0,
            const float* __restrict__ f1,
            const float* __restrict__ f2,
            const float* __restrict__ f3,
            float* __restrict__ out)
{
    const int r = blockIdx.x, b = blockIdx.y;
    const int roi = b * RSEL + r;
    const int tid = threadIdx.x;
    const int warp = tid >> 5, lane = tid & 31;

    __shared__ float swx[MAXSPAN];
    __shared__ int   srows[MAXROWS];
    __shared__ float srwt[MAXROWS];
    __shared__ int4  smeta;

    if (tid < MAXSPAN)                          swx[tid] = g_wx[roi][tid];
    else if (tid < MAXSPAN + MAXROWS)           srows[tid - MAXSPAN] = g_rows[roi][tid - MAXSPAN];
    else if (tid < MAXSPAN + 2 * MAXROWS)       srwt[tid - MAXSPAN - MAXROWS] = g_rwt[roi][tid - MAXSPAN - MAXROWS];
    else if (tid == MAXSPAN + 2 * MAXROWS)      smeta = g_meta[roi];
    __syncthreads();

    const int Kr   = smeta.x;
    const int xmin = smeta.y;
    const int xmax = smeta.z;
    const int lv   = smeta.w;

    const int Hs[4] = {200, 100, 50, 25};
    const int H = Hs[lv], W = H;
    const float* fbase =
        (lv == 0 ? f0 : lv == 1 ? f1 : lv == 2 ? f2 : f3) + (size_t)b * CCH * H * W;

    const int cbase = blockIdx.z * 32 + warp * 4;
    const float* cp0 = fbase + (size_t)(cbase + 0) * H * W;
    const float* cp1 = fbase + (size_t)(cbase + 1) * H * W;
    const float* cp2 = fbase + (size_t)(cbase + 2) * H * W;
    const float* cp3 = fbase + (size_t)(cbase + 3) * H * W;

    const int x0 = xmin + lane;
    const int x1 = x0 + 32;
    const bool a0 = (x0 <= xmax);
    const bool a1 = (x1 <= xmax);
    const float w0 = a0 ? swx[lane] : 0.0f;
    const float w1 = a1 ? swx[lane + 32] : 0.0f;

    float acc0 = 0.0f, acc1 = 0.0f, acc2 = 0.0f, acc3 = 0.0f;
    #pragma unroll 2
    for (int j = 0; j < Kr; j++) {
        const int ro = srows[j] * W;
        const float rw = srwt[j];
        float s0 = 0.f, s1 = 0.f, s2 = 0.f, s3 = 0.f;
        if (a0) {
            s0 = cp0[ro + x0] * w0;
            s1 = cp1[ro + x0] * w0;
            s2 = cp2[ro + x0] * w0;
            s3 = cp3[ro + x0] * w0;
        }
        if (a1) {
            s0 += cp0[ro + x1] * w1;
            s1 += cp1[ro + x1] * w1;
            s2 += cp2[ro + x1] * w1;
            s3 += cp3[ro + x1] * w1;
        }
        acc0 += rw * s0;
        acc1 += rw * s1;
        acc2 += rw * s2;
        acc3 += rw * s3;
    }

    #pragma unroll
    for (int o = 16; o > 0; o >>= 1) {
        acc0 += __shfl_xor_sync(0xffffffffu, acc0, o);
        acc1 += __shfl_xor_sync(0xffffffffu, acc1, o);
        acc2 += __shfl_xor_sync(0xffffffffu, acc2, o);
        acc3 += __shfl_xor_sync(0xffffffffu, acc3, o);
    }

    if (lane == 0) {
        float* op = out + (size_t)roi * CCH + cbase;
        op[0] = acc0 * (1.0f / 196.0f);
        op[1] = acc1 * (1.0f / 196.0f);
        op[2] = acc2 * (1.0f / 196.0f);
        op[3] = acc3 * (1.0f / 196.0f);
    }
}

// ---------------------------------------------------------------------------
extern "C" void kernel_launch(void* const* d_in, const int* in_sizes, int n_in,
                              void* d_out, int out_size)
{
    const float* boxes  = (const float*)d_in[0];
    const float* scores = (const float*)d_in[1];
    const float* f0     = (const float*)d_in[2];
    const float* f1     = (const float*)d_in[3];
    const float* f2     = (const float*)d_in[4];
    const float* f3     = (const float*)d_in[5];
    float* out = (float*)d_out;

    select_kernel<<<BB, SELTHR>>>(boxes, scores);
    pool_kernel<<<dim3(RSEL, BB, 8), 256>>>(f0, f1, f2, f3, out);
}

// round 9
// speedup vs baseline: 1.3471x; 1.3471x over previous
#include <cuda_runtime.h>
#include <math.h>

#define BB 8
#define NBOX 300
#define RSEL 36
#define CCH 256
#define NROI (BB * RSEL)
#define IOU_THRS 0.7f
#define CONF_THRS 0.3f
#define GRIDP 14     // OUT*SR
#define NWORDS 10    // ceil(300/32)
#define MAXROWS 28   // 14 samples x 2 taps
#define MAXSPAN 64

// ---- scratch (device globals; no allocs) ----
__device__ float4        g_sbox[BB][NBOX];           // sorted boxes (written by t=0 blocks)
__device__ int           g_sval[BB][NBOX];           // valid flag
__device__ unsigned int  g_sup[BB][NWORDS][NBOX];    // word-major suppression bits

__device__ float g_wx[NROI][MAXSPAN];
__device__ int   g_rows[NROI][MAXROWS];
__device__ float g_rwt[NROI][MAXROWS];
__device__ int4  g_meta[NROI];                        // {Kr, xmin, xmax, lv}

__device__ __forceinline__ float neg_inf() { return __int_as_float(0xff800000); }

// ---------------------------------------------------------------------------
// Kernel A: fused sort + suppression word build.
// Grid (NWORDS, BB) = 80 blocks. Each block redundantly ranks its batch in
// shared (parallel wall-clock), then computes suppression word t for all rows.
// Blocks with t==0 export sorted boxes + valid flags for the NMS kernel.
// ---------------------------------------------------------------------------
__global__ void __launch_bounds__(320)
iou_kernel(const float* __restrict__ boxes,
           const float* __restrict__ scores)
{
    const int t   = blockIdx.x;   // word index 0..9
    const int b   = blockIdx.y;
    const int tid = threadIdx.x;

    __shared__ float         s[NBOX];
    __shared__ float4        bx[NBOX];
    __shared__ unsigned char val[NBOX];

    if (tid < NBOX) {
        float sc = scores[b * NBOX + tid];
        s[tid] = (sc > CONF_THRS) ? sc : neg_inf();
    }
    __syncthreads();

    // stable descending rank -> sorted boxes in shared
    if (tid < NBOX) {
        const float mys = s[tid];
        int rank = 0;
        #pragma unroll 4
        for (int k = 0; k < NBOX; k++) {
            float sk = s[k];
            rank += (sk > mys) || (sk == mys && k < tid);
        }
        const float* bp = boxes + (size_t)(b * NBOX + tid) * 4;
        bx[rank]  = make_float4(bp[0], bp[1], bp[2], bp[3]);
        val[rank] = (mys > CONF_THRS) ? 1 : 0;
    }
    __syncthreads();

    // suppression word t for row i = tid
    if (tid < NBOX) {
        const float4 a = bx[tid];
        const float areaA = __fmul_rn(__fsub_rn(a.z, a.x), __fsub_rn(a.w, a.y));
        unsigned int w = 0;
        const int j0 = t * 32;
        #pragma unroll 4
        for (int jj = 0; jj < 32; jj++) {
            const int j = j0 + jj;
            if (j > tid && j < NBOX) {
                float4 bb = bx[j];
                float areaB = __fmul_rn(__fsub_rn(bb.z, bb.x), __fsub_rn(bb.w, bb.y));
                float ltx = fmaxf(a.x, bb.x), lty = fmaxf(a.y, bb.y);
                float rbx = fminf(a.z, bb.z), rby = fminf(a.w, bb.w);
                float iw = fmaxf(__fsub_rn(rbx, ltx), 0.0f);
                float ih = fmaxf(__fsub_rn(rby, lty), 0.0f);
                float inter = __fmul_rn(iw, ih);
                float den = __fadd_rn(__fsub_rn(__fadd_rn(areaA, areaB), inter), 1e-9f);
                float iou = __fdiv_rn(inter, den);
                if (iou > IOU_THRS) w |= (1u << jj);
            }
        }
        g_sup[b][t][tid] = w;

        if (t == 0) {
            g_sbox[b][tid] = a;
            g_sval[b][tid] = val[tid];
        }
    }
}

// ---------------------------------------------------------------------------
// Kernel B: serial greedy NMS + stable partition + level + fused per-ROI prep
// ---------------------------------------------------------------------------
__global__ void nms_kernel()
{
    const int b   = blockIdx.x;
    const int tid = threadIdx.x;

    __shared__ unsigned int ssup[NWORDS * NBOX];   // [t][i]
    __shared__ unsigned int keepW[NWORDS];
    __shared__ float4 sselBox[RSEL];
    __shared__ int    sselLv[RSEL];
    __shared__ int    sselValid[RSEL];

    // stage suppression matrix (coalesced)
    const unsigned int* gsup = &g_sup[b][0][0];
    for (int k = tid; k < NWORDS * NBOX; k += blockDim.x)
        ssup[k] = gsup[k];

    // initial keep bits
    if (tid < NWORDS) {
        unsigned int w = 0;
        for (int jj = 0; jj < 32; jj++) {
            int j = tid * 32 + jj;
            if (j < NBOX && g_sval[b][j]) w |= (1u << jj);
        }
        keepW[tid] = w;
    }
    __syncthreads();

    // serial greedy pass: all 300 keep-bits live in one thread's registers
    if (tid == 0) {
        unsigned int kw[NWORDS];
        #pragma unroll
        for (int t = 0; t < NWORDS; t++) kw[t] = keepW[t];
        for (int i = 0; i < NBOX; i++) {
            if ((kw[i >> 5] >> (i & 31)) & 1u) {
                #pragma unroll
                for (int t = 0; t < NWORDS; t++)
                    kw[t] &= ~ssup[t * NBOX + i];
            }
        }
        #pragma unroll
        for (int t = 0; t < NWORDS; t++) keepW[t] = kw[t];
    }
    __syncthreads();

    // stable partition select: kept (in order) first, then dropped (in order)
    if (tid < NBOX) {
        const int w = tid >> 5, bit = tid & 31;
        int kept_before = 0;
        for (int t = 0; t < w; t++) kept_before += __popc(keepW[t]);
        kept_before += __popc(keepW[w] & ((1u << bit) - 1u));
        const bool mykeep = (keepW[w] >> bit) & 1u;
        int totKept = 0;
        for (int t = 0; t < NWORDS; t++) totKept += __popc(keepW[t]);

        int pos = mykeep ? kept_before : (totKept + (tid - kept_before));
        if (pos < RSEL) {
            float4 bx = g_sbox[b][tid];
            sselBox[pos]   = bx;
            sselValid[pos] = mykeep ? 1 : 0;
            float dx = __fsub_rn(bx.z, bx.x), dy = __fsub_rn(bx.w, bx.y);
            float ss = __fadd_rn(__fmul_rn(dx, dx), __fmul_rn(dy, dy));
            float size = sqrtf(fmaxf(ss, 1e-12f));
            float t = floorf(__fadd_rn(4.0f, log2f(__fmul_rn(__fdiv_rn(size, 224.0f), 4.0f))));
            t = fminf(fmaxf(t, 2.0f), 5.0f);
            sselLv[pos] = (int)t - 2;
        }
    }
    __syncthreads();

    // fused per-ROI pooling plan (threads 0..RSEL-1)
    if (tid < RSEL) {
        const int r   = tid;
        const int roi = b * RSEL + r;

        float wx[MAXSPAN];
        #pragma unroll
        for (int i = 0; i < MAXSPAN; i++) wx[i] = 0.0f;

        int Kr = 0, xmin = 0, xmax = -1;
        const int lv = sselLv[r];
        int   rows[MAXROWS];
        float rwt[MAXROWS];

        if (sselValid[r]) {
            const int Hs[4] = {200, 100, 50, 25};
            const int H = Hs[lv], W = H;
            const float4 bx = sselBox[r];
            const float rw = fmaxf(__fsub_rn(bx.z, bx.x), 1.0f);
            const float rh = fmaxf(__fsub_rn(bx.w, bx.y), 1.0f);

            int xm = 0x7fffffff, xM = -1;
            int ix0s[GRIDP], ix1s[GRIDP];
            float lxs[GRIDP], mxs[GRIDP];
            for (int k = 0; k < GRIDP; k++) {
                float g = (k + 0.5f) / (float)GRIDP;
                float X = __fadd_rn(bx.x, __fmul_rn(rw, g));
                float mx = (X < -1.0f || X > (float)W) ? 0.0f : 1.0f;
                float x = fminf(fmaxf(X, 0.0f), (float)(W - 1));
                int i0 = (int)floorf(x);
                int i1 = min(i0 + 1, W - 1);
                ix0s[k] = i0; ix1s[k] = i1;
                lxs[k] = __fsub_rn(x, (float)i0); mxs[k] = mx;
                if (mx > 0.0f) { if (i0 < xm) xm = i0; if (i1 > xM) xM = i1; }
            }
            if (xM >= xm && (xM - xm) < MAXSPAN) {
                for (int k = 0; k < GRIDP; k++) {
                    if (mxs[k] == 0.0f) continue;
                    wx[ix0s[k] - xm] += __fmul_rn(1.0f - lxs[k], mxs[k]);
                    wx[ix1s[k] - xm] += __fmul_rn(lxs[k], mxs[k]);
                }
                xmin = xm; xmax = xM;

                for (int k = 0; k < GRIDP; k++) {
                    float g = (k + 0.5f) / (float)GRIDP;
                    float Y = __fadd_rn(bx.y, __fmul_rn(rh, g));
                    float my = (Y < -1.0f || Y > (float)H) ? 0.0f : 1.0f;
                    float y = fminf(fmaxf(Y, 0.0f), (float)(H - 1));
                    int iy0 = (int)floorf(y);
                    int iy1 = min(iy0 + 1, H - 1);
                    float ly = __fsub_rn(y, (float)iy0);
                    float w0 = __fmul_rn(1.0f - ly, my);
                    float w1 = __fmul_rn(ly, my);
                    for (int tt = 0; tt < 2; tt++) {
                        int   row = tt ? iy1 : iy0;
                        float wv  = tt ? w1 : w0;
                        if (wv == 0.0f) continue;
                        int found = -1;
                        for (int q = 0; q < Kr; q++)
                            if (rows[q] == row) { found = q; break; }
                        if (found >= 0) rwt[found] += wv;
                        else if (Kr < MAXROWS) { rows[Kr] = row; rwt[Kr] = wv; Kr++; }
                    }
                }
            }
        }

        for (int i = 0; i < MAXSPAN; i++) g_wx[roi][i] = wx[i];
        for (int i = 0; i < MAXROWS; i++) {
            g_rows[roi][i] = (i < Kr) ? rows[i] : 0;
            g_rwt[roi][i]  = (i < Kr) ? rwt[i]  : 0.0f;
        }
        g_meta[roi] = make_int4(Kr, xmin, xmax, lv);
    }
}

// ---------------------------------------------------------------------------
// Kernel C: pooling. One warp per (roi, channel). grid (RSEL, BB, 32).
// (exact R5 configuration — 22.7us, DRAM 20%, occ 69%)
// ---------------------------------------------------------------------------
__global__ void __launch_bounds__(256)
pool_kernel(const float* __restrict__ f0,
            const float* __restrict__ f1,
            const float* __restrict__ f2,
            const float* __restrict__ f3,
            float* __restrict__ out)
{
    const int r = blockIdx.x, b = blockIdx.y;
    const int roi = b * RSEL + r;
    const int tid = threadIdx.x;
    const int warp = tid >> 5, lane = tid & 31;

    __shared__ float swx[MAXSPAN];
    __shared__ int   srows[MAXROWS];
    __shared__ float srwt[MAXROWS];
    __shared__ int4  smeta;

    if (tid < MAXSPAN)                          swx[tid] = g_wx[roi][tid];
    else if (tid < MAXSPAN + MAXROWS)           srows[tid - MAXSPAN] = g_rows[roi][tid - MAXSPAN];
    else if (tid < MAXSPAN + 2 * MAXROWS)       srwt[tid - MAXSPAN - MAXROWS] = g_rwt[roi][tid - MAXSPAN - MAXROWS];
    else if (tid == MAXSPAN + 2 * MAXROWS)      smeta = g_meta[roi];
    __syncthreads();

    const int Kr   = smeta.x;
    const int xmin = smeta.y;
    const int xmax = smeta.z;
    const int lv   = smeta.w;

    const int Hs[4] = {200, 100, 50, 25};
    const int H = Hs[lv], W = H;
    const float* fbase =
        (lv == 0 ? f0 : lv == 1 ? f1 : lv == 2 ? f2 : f3) + (size_t)b * CCH * H * W;

    const int c = blockIdx.z * 8 + warp;
    const float* cp = fbase + (size_t)c * H * W;

    const int x0 = xmin + lane;
    const int x1 = x0 + 32;
    const bool a0 = (x0 <= xmax);
    const bool a1 = (x1 <= xmax);
    const float w0 = a0 ? swx[lane] : 0.0f;
    const float w1 = a1 ? swx[lane + 32] : 0.0f;

    float acc = 0.0f;
    #pragma unroll 4
    for (int j = 0; j < Kr; j++) {
        const float* rp = cp + srows[j] * W;
        float s = 0.0f;
        if (a0) s = rp[x0] * w0;
        if (a1) s += rp[x1] * w1;
        acc += srwt[j] * s;
    }

    #pragma unroll
    for (int o = 16; o > 0; o >>= 1)
        acc += __shfl_xor_sync(0xffffffffu, acc, o);

    if (lane == 0)
        out[(size_t)roi * CCH + c] = acc * (1.0f / 196.0f);
}

// ---------------------------------------------------------------------------
extern "C" void kernel_launch(void* const* d_in, const int* in_sizes, int n_in,
                              void* d_out, int out_size)
{
    const float* boxes  = (const float*)d_in[0];
    const float* scores = (const float*)d_in[1];
    const float* f0     = (const float*)d_in[2];
    const float* f1     = (const float*)d_in[3];
    const float* f2     = (const float*)d_in[4];
    const float* f3     = (const float*)d_in[5];
    float* out = (float*)d_out;

    iou_kernel<<<dim3(NWORDS, BB), 320>>>(boxes, scores);
    nms_kernel<<<BB, 320>>>();
    pool_kernel<<<dim3(RSEL, BB, 32), 256>>>(f0, f1, f2, f3, out);
}

// round 10
// speedup vs baseline: 1.7503x; 1.2993x over previous
#include <cuda_runtime.h>
#include <math.h>

#define BB 8
#define NBOX 300
#define RSEL 36
#define CCH 256
#define NROI (BB * RSEL)
#define IOU_THRS 0.7f
#define CONF_THRS 0.3f
#define GRIDP 14     // OUT*SR
#define NWORDS 10    // ceil(300/32)
#define SUPW 12      // padded row width (48B = 3 x uint4)
#define MAXROWS 28
#define MAXSPAN 64
#define IOUTHR 640

// ---- scratch (device globals; no allocs) ----
__device__ float4        g_sbox[BB][NBOX];
__device__ int           g_sval[BB][NBOX];
__device__ unsigned int  g_sup[BB][NBOX][SUPW];   // ROW-major, 16B-aligned rows

__device__ float g_wx[NROI][MAXSPAN];
__device__ int   g_rows[NROI][MAXROWS];
__device__ float g_rwt[NROI][MAXROWS];
__device__ int4  g_meta[NROI];                     // {Kr, xmin, xmax, lv}

__device__ __forceinline__ float neg_inf() { return __int_as_float(0xff800000); }

// ---------------------------------------------------------------------------
// Kernel A: fused sort (2-way split rank) + suppression words (2 per block).
// Grid (5, BB), 640 threads.
// ---------------------------------------------------------------------------
__global__ void __launch_bounds__(IOUTHR)
iou_kernel(const float* __restrict__ boxes,
           const float* __restrict__ scores)
{
    const int t2  = blockIdx.x;   // word pair 0..4 -> words 2*t2, 2*t2+1
    const int b   = blockIdx.y;
    const int tid = threadIdx.x;

    __shared__ float         s[NBOX];
    __shared__ float4        bx[NBOX];
    __shared__ unsigned char val[NBOX];
    __shared__ short         prank[NBOX];

    if (tid < NBOX) {
        float sc = scores[b * NBOX + tid];
        s[tid] = (sc > CONF_THRS) ? sc : neg_inf();
    }
    __syncthreads();

    // ---- split stable-descending rank: two threads per box, 150 elems each
    int box = -1, k0 = 0, k1 = 0;
    if (tid < NBOX)                       { box = tid;       k0 = 0;   k1 = 150; }
    else if (tid >= 320 && tid < 320+NBOX){ box = tid - 320; k0 = 150; k1 = NBOX; }

    int myrank = 0;
    if (box >= 0) {
        const float mys = s[box];
        #pragma unroll 4
        for (int k = k0; k < k1; k++) {
            float sk = s[k];
            myrank += (sk > mys) || (sk == mys && k < box);
        }
        if (tid >= 320) prank[box] = (short)myrank;
    }
    __syncthreads();

    if (tid < NBOX) {
        const int rank = myrank + (int)prank[tid];
        const float* bp = boxes + (size_t)(b * NBOX + tid) * 4;
        bx[rank]  = make_float4(bp[0], bp[1], bp[2], bp[3]);
        val[rank] = (s[tid] > CONF_THRS) ? 1 : 0;
    }
    __syncthreads();

    // ---- suppression: word w = 2*t2 + (tid>=320), row i
    const int half = (tid >= 320) ? 1 : 0;
    const int i    = tid - half * 320;
    const int w    = 2 * t2 + half;
    if (i < NBOX) {
        const float4 a = bx[i];
        const float areaA = __fmul_rn(__fsub_rn(a.z, a.x), __fsub_rn(a.w, a.y));
        unsigned int wb = 0;
        const int j0 = w * 32;
        #pragma unroll 4
        for (int jj = 0; jj < 32; jj++) {
            const int j = j0 + jj;
            if (j > i && j < NBOX) {
                float4 bb = bx[j];
                float areaB = __fmul_rn(__fsub_rn(bb.z, bb.x), __fsub_rn(bb.w, bb.y));
                float ltx = fmaxf(a.x, bb.x), lty = fmaxf(a.y, bb.y);
                float rbx = fminf(a.z, bb.z), rby = fminf(a.w, bb.w);
                float iw = fmaxf(__fsub_rn(rbx, ltx), 0.0f);
                float ih = fmaxf(__fsub_rn(rby, lty), 0.0f);
                float inter = __fmul_rn(iw, ih);
                float den = __fadd_rn(__fsub_rn(__fadd_rn(areaA, areaB), inter), 1e-9f);
                float iou = __fdiv_rn(inter, den);
                if (iou > IOU_THRS) wb |= (1u << jj);
            }
        }
        g_sup[b][i][w] = wb;
        if (t2 == 0 && half == 0) {
            g_sbox[b][i] = a;
            g_sval[b][i] = val[i];
            g_sup[b][i][10] = 0;           // pad words
            g_sup[b][i][11] = 0;
        }
    }
}

// ---------------------------------------------------------------------------
// Kernel B: serial greedy NMS (uint4 rows, early exit) + partition + prep
// ---------------------------------------------------------------------------
__global__ void __launch_bounds__(320)
nms_kernel()
{
    const int b   = blockIdx.x;
    const int tid = threadIdx.x;

    __shared__ uint4         ssup[NBOX * 3];      // row-major: row i = ssup[3i..3i+2]
    __shared__ unsigned int  keepW[NWORDS];
    __shared__ float4 sselBox[RSEL];
    __shared__ int    sselLv[RSEL];
    __shared__ int    sselValid[RSEL];

    // stage suppression matrix as uint4 (coalesced)
    const uint4* gsup = (const uint4*)&g_sup[b][0][0];
    for (int k = tid; k < NBOX * 3; k += 320)
        ssup[k] = gsup[k];

    if (tid < NWORDS) {
        unsigned int w = 0;
        for (int jj = 0; jj < 32; jj++) {
            int j = tid * 32 + jj;
            if (j < NBOX && g_sval[b][j]) w |= (1u << jj);
        }
        keepW[tid] = w;
    }
    __syncthreads();

    // serial greedy pass with early exit after RSEL kept
    if (tid == 0) {
        unsigned int kw[NWORDS];
        #pragma unroll
        for (int t = 0; t < NWORDS; t++) kw[t] = keepW[t];
        int cnt = 0;
        for (int i = 0; i < NBOX; i++) {
            if ((kw[i >> 5] >> (i & 31)) & 1u) {
                const uint4 m0 = ssup[i * 3 + 0];
                const uint4 m1 = ssup[i * 3 + 1];
                const uint4 m2 = ssup[i * 3 + 2];
                kw[0] &= ~m0.x; kw[1] &= ~m0.y; kw[2] &= ~m0.z; kw[3] &= ~m0.w;
                kw[4] &= ~m1.x; kw[5] &= ~m1.y; kw[6] &= ~m1.z; kw[7] &= ~m1.w;
                kw[8] &= ~m2.x; kw[9] &= ~m2.y;
                if (++cnt == RSEL) break;   // later boxes all land at pos >= RSEL
            }
        }
        #pragma unroll
        for (int t = 0; t < NWORDS; t++) keepW[t] = kw[t];
    }
    __syncthreads();

    // stable partition select
    if (tid < NBOX) {
        const int w = tid >> 5, bit = tid & 31;
        int kept_before = 0;
        for (int t = 0; t < w; t++) kept_before += __popc(keepW[t]);
        kept_before += __popc(keepW[w] & ((1u << bit) - 1u));
        const bool mykeep = (keepW[w] >> bit) & 1u;
        int totKept = 0;
        for (int t = 0; t < NWORDS; t++) totKept += __popc(keepW[t]);

        int pos = mykeep ? kept_before : (totKept + (tid - kept_before));
        if (pos < RSEL) {
            float4 bx = g_sbox[b][tid];
            sselBox[pos]   = bx;
            sselValid[pos] = mykeep ? 1 : 0;
            float dx = __fsub_rn(bx.z, bx.x), dy = __fsub_rn(bx.w, bx.y);
            float ss = __fadd_rn(__fmul_rn(dx, dx), __fmul_rn(dy, dy));
            float size = sqrtf(fmaxf(ss, 1e-12f));
            float t = floorf(__fadd_rn(4.0f, log2f(__fmul_rn(__fdiv_rn(size, 224.0f), 4.0f))));
            t = fminf(fmaxf(t, 2.0f), 5.0f);
            sselLv[pos] = (int)t - 2;
        }
    }
    __syncthreads();

    // fused per-ROI pooling plan
    if (tid < RSEL) {
        const int r   = tid;
        const int roi = b * RSEL + r;

        float wx[MAXSPAN];
        #pragma unroll
        for (int i = 0; i < MAXSPAN; i++) wx[i] = 0.0f;

        int Kr = 0, xmin = 0, xmax = -1;
        const int lv = sselLv[r];
        int   rows[MAXROWS];
        float rwt[MAXROWS];

        if (sselValid[r]) {
            const int Hs[4] = {200, 100, 50, 25};
            const int H = Hs[lv], W = H;
            const float4 bx = sselBox[r];
            const float rw = fmaxf(__fsub_rn(bx.z, bx.x), 1.0f);
            const float rh = fmaxf(__fsub_rn(bx.w, bx.y), 1.0f);

            int xm = 0x7fffffff, xM = -1;
            int ix0s[GRIDP], ix1s[GRIDP];
            float lxs[GRIDP], mxs[GRIDP];
            for (int k = 0; k < GRIDP; k++) {
                float g = (k + 0.5f) / (float)GRIDP;
                float X = __fadd_rn(bx.x, __fmul_rn(rw, g));
                float mx = (X < -1.0f || X > (float)W) ? 0.0f : 1.0f;
                float x = fminf(fmaxf(X, 0.0f), (float)(W - 1));
                int i0 = (int)floorf(x);
                int i1 = min(i0 + 1, W - 1);
                ix0s[k] = i0; ix1s[k] = i1;
                lxs[k] = __fsub_rn(x, (float)i0); mxs[k] = mx;
                if (mx > 0.0f) { if (i0 < xm) xm = i0; if (i1 > xM) xM = i1; }
            }
            if (xM >= xm && (xM - xm) < MAXSPAN) {
                for (int k = 0; k < GRIDP; k++) {
                    if (mxs[k] == 0.0f) continue;
                    wx[ix0s[k] - xm] += __fmul_rn(1.0f - lxs[k], mxs[k]);
                    wx[ix1s[k] - xm] += __fmul_rn(lxs[k], mxs[k]);
                }
                xmin = xm; xmax = xM;

                for (int k = 0; k < GRIDP; k++) {
                    float g = (k + 0.5f) / (float)GRIDP;
                    float Y = __fadd_rn(bx.y, __fmul_rn(rh, g));
                    float my = (Y < -1.0f || Y > (float)H) ? 0.0f : 1.0f;
                    float y = fminf(fmaxf(Y, 0.0f), (float)(H - 1));
                    int iy0 = (int)floorf(y);
                    int iy1 = min(iy0 + 1, H - 1);
                    float ly = __fsub_rn(y, (float)iy0);
                    float w0 = __fmul_rn(1.0f - ly, my);
                    float w1 = __fmul_rn(ly, my);
                    for (int tt = 0; tt < 2; tt++) {
                        int   row = tt ? iy1 : iy0;
                        float wv  = tt ? w1 : w0;
                        if (wv == 0.0f) continue;
                        int found = -1;
                        for (int q = 0; q < Kr; q++)
                            if (rows[q] == row) { found = q; break; }
                        if (found >= 0) rwt[found] += wv;
                        else if (Kr < MAXROWS) { rows[Kr] = row; rwt[Kr] = wv; Kr++; }
                    }
                }
            }
        }

        for (int i = 0; i < MAXSPAN; i++) g_wx[roi][i] = wx[i];
        for (int i = 0; i < MAXROWS; i++) {
            g_rows[roi][i] = (i < Kr) ? rows[i] : 0;
            g_rwt[roi][i]  = (i < Kr) ? rwt[i]  : 0.0f;
        }
        g_meta[roi] = make_int4(Kr, xmin, xmax, lv);
    }
}

// ---------------------------------------------------------------------------
// Kernel C: pooling. One warp per (roi, channel). grid (RSEL, BB, 32).
// (exact R5 configuration — 22.7us)
// ---------------------------------------------------------------------------
__global__ void __launch_bounds__(256)
pool_kernel(const float* __restrict__ f0,
            const float* __restrict__ f1,
            const float* __restrict__ f2,
            const float* __restrict__ f3,
            float* __restrict__ out)
{
    const int r = blockIdx.x, b = blockIdx.y;
    const int roi = b * RSEL + r;
    const int tid = threadIdx.x;
    const int warp = tid >> 5, lane = tid & 31;

    __shared__ float swx[MAXSPAN];
    __shared__ int   srows[MAXROWS];
    __shared__ float srwt[MAXROWS];
    __shared__ int4  smeta;

    if (tid < MAXSPAN)                          swx[tid] = g_wx[roi][tid];
    else if (tid < MAXSPAN + MAXROWS)           srows[tid - MAXSPAN] = g_rows[roi][tid - MAXSPAN];
    else if (tid < MAXSPAN + 2 * MAXROWS)       srwt[tid - MAXSPAN - MAXROWS] = g_rwt[roi][tid - MAXSPAN - MAXROWS];
    else if (tid == MAXSPAN + 2 * MAXROWS)      smeta = g_meta[roi];
    __syncthreads();

    const int Kr   = smeta.x;
    const int xmin = smeta.y;
    const int xmax = smeta.z;
    const int lv   = smeta.w;

    const int Hs[4] = {200, 100, 50, 25};
    const int H = Hs[lv], W = H;
    const float* fbase =
        (lv == 0 ? f0 : lv == 1 ? f1 : lv == 2 ? f2 : f3) + (size_t)b * CCH * H * W;

    const int c = blockIdx.z * 8 + warp;
    const float* cp = fbase + (size_t)c * H * W;

    const int x0 = xmin + lane;
    const int x1 = x0 + 32;
    const bool a0 = (x0 <= xmax);
    const bool a1 = (x1 <= xmax);
    const float w0 = a0 ? swx[lane] : 0.0f;
    const float w1 = a1 ? swx[lane + 32] : 0.0f;

    float acc = 0.0f;
    #pragma unroll 4
    for (int j = 0; j < Kr; j++) {
        const float* rp = cp + srows[j] * W;
        float s = 0.0f;
        if (a0) s = rp[x0] * w0;
        if (a1) s += rp[x1] * w1;
        acc += srwt[j] * s;
    }

    #pragma unroll
    for (int o = 16; o > 0; o >>= 1)
        acc += __shfl_xor_sync(0xffffffffu, acc, o);

    if (lane == 0)
        out[(size_t)roi * CCH + c] = acc * (1.0f / 196.0f);
}

// ---------------------------------------------------------------------------
extern "C" void kernel_launch(void* const* d_in, const int* in_sizes, int n_in,
                              void* d_out, int out_size)
{
    const float* boxes  = (const float*)d_in[0];
    const float* scores = (const float*)d_in[1];
    const float* f0     = (const float*)d_in[2];
    const float* f1     = (const float*)d_in[3];
    const float* f2     = (const float*)d_in[4];
    const float* f3     = (const float*)d_in[5];
    float* out = (float*)d_out;

    iou_kernel<<<dim3(5, BB), IOUTHR>>>(boxes, scores);
    nms_kernel<<<BB, 320>>>();
    pool_kernel<<<dim3(RSEL, BB, 32), 256>>>(f0, f1, f2, f3, out);
}

// round 11
// speedup vs baseline: 1.8847x; 1.0768x over previous
#include <cuda_runtime.h>
#include <math.h>

#define BB 8
#define NBOX 300
#define RSEL 36
#define CCH 256
#define NROI (BB * RSEL)
#define IOU_THRS 0.7f
#define CONF_THRS 0.3f
#define GRIDP 14     // OUT*SR
#define NWORDS 10    // ceil(300/32)
#define SUPW 12      // padded row width (48B = 3 x uint4)
#define MAXROWS 28
#define MAXSPAN 64
#define SELTHR 640

// ---- scratch (device globals; no allocs) ----
__device__ unsigned int  g_sup[BB][NBOX][SUPW];   // row-major, 16B-aligned rows
__device__ int           g_done[BB];              // zero-init; reset by consumer

__device__ float g_wx[NROI][MAXSPAN];
__device__ int   g_rows[NROI][MAXROWS];
__device__ float g_rwt[NROI][MAXROWS];
__device__ int4  g_meta[NROI];                     // {Kr, xmin, xmax, lv}

__device__ __forceinline__ float neg_inf() { return __int_as_float(0xff800000); }

// ---------------------------------------------------------------------------
// Kernel A (fused): sort + suppression word (jj-split halves) + in-kernel NMS.
// Grid (NWORDS, BB) = 80 blocks x 640 threads. Block (t,b) computes word t.
// Block t==0 of each batch waits for its 9 peers, then does serial NMS +
// stable partition + per-ROI prep entirely from shared-resident sorted boxes.
// ---------------------------------------------------------------------------
__global__ void __launch_bounds__(SELTHR)
select_kernel(const float* __restrict__ boxes,
              const float* __restrict__ scores)
{
    const int t   = blockIdx.x;   // word 0..9
    const int b   = blockIdx.y;
    const int tid = threadIdx.x;

    __shared__ float         s[NBOX];
    __shared__ float4        bx[NBOX];
    __shared__ unsigned char val[NBOX];
    __shared__ short         prank[NBOX];
    __shared__ unsigned int  part[NBOX];          // jj-half merge
    // nms-only (t==0 blocks)
    __shared__ uint4         ssup[NBOX * 3];
    __shared__ unsigned int  keepW[NWORDS];
    __shared__ float4 sselBox[RSEL];
    __shared__ int    sselLv[RSEL];
    __shared__ int    sselValid[RSEL];

    if (tid < NBOX) {
        float sc = scores[b * NBOX + tid];
        s[tid] = (sc > CONF_THRS) ? sc : neg_inf();
    }
    __syncthreads();

    // ---- split stable-descending rank: two threads per box, 150 elems each
    int box = -1, k0 = 0, k1 = 0;
    if (tid < NBOX)                        { box = tid;       k0 = 0;   k1 = 150; }
    else if (tid >= 320 && tid < 320+NBOX) { box = tid - 320; k0 = 150; k1 = NBOX; }

    int myrank = 0;
    if (box >= 0) {
        const float mys = s[box];
        #pragma unroll 4
        for (int k = k0; k < k1; k++) {
            float sk = s[k];
            myrank += (sk > mys) || (sk == mys && k < box);
        }
        if (tid >= 320) prank[box] = (short)myrank;
    }
    __syncthreads();

    if (tid < NBOX) {
        const int rank = myrank + (int)prank[tid];
        const float* bp = boxes + (size_t)(b * NBOX + tid) * 4;
        bx[rank]  = make_float4(bp[0], bp[1], bp[2], bp[3]);
        val[rank] = (s[tid] > CONF_THRS) ? 1 : 0;
    }
    __syncthreads();

    // ---- suppression word t, jj split across thread halves (16 evals each)
    const int half = (tid >= 320) ? 1 : 0;
    const int i    = tid - half * 320;
    unsigned int wb = 0;
    if (i < NBOX) {
        const float4 a = bx[i];
        const float areaA = __fmul_rn(__fsub_rn(a.z, a.x), __fsub_rn(a.w, a.y));
        const int jjb = half * 16;
        #pragma unroll 4
        for (int q = 0; q < 16; q++) {
            const int jj = jjb + q;
            const int j  = t * 32 + jj;
            if (j > i && j < NBOX) {
                float4 bb = bx[j];
                float areaB = __fmul_rn(__fsub_rn(bb.z, bb.x), __fsub_rn(bb.w, bb.y));
                float ltx = fmaxf(a.x, bb.x), lty = fmaxf(a.y, bb.y);
                float rbx = fminf(a.z, bb.z), rby = fminf(a.w, bb.w);
                float iw = fmaxf(__fsub_rn(rbx, ltx), 0.0f);
                float ih = fmaxf(__fsub_rn(rby, lty), 0.0f);
                float inter = __fmul_rn(iw, ih);
                float den = __fadd_rn(__fsub_rn(__fadd_rn(areaA, areaB), inter), 1e-9f);
                float iou = __fdiv_rn(inter, den);
                if (iou > IOU_THRS) wb |= (1u << jj);
            }
        }
        if (half) part[i] = wb;
    }
    __syncthreads();

    if (half == 0 && i < NBOX) {
        g_sup[b][i][t] = wb | part[i];
        if (t == 0) {                      // zero pad words once
            g_sup[b][i][10] = 0;
            g_sup[b][i][11] = 0;
        }
    }
    // publish: all writes visible, then count this block as done
    __threadfence();
    __syncthreads();
    if (tid == 0) atomicAdd(&g_done[b], 1);

    if (t != 0) return;                    // 9 of 10 blocks exit here

    // ================= t==0 block: in-kernel NMS =================
    if (tid == 0) {
        while (atomicAdd(&g_done[b], 0) < NWORDS) { }
        atomicExch(&g_done[b], 0);         // single consumer -> safe reset
        __threadfence();
    }
    __syncthreads();

    // stage suppression matrix (bypass L1 — written by peer blocks)
    const uint4* gsup = (const uint4*)&g_sup[b][0][0];
    for (int k = tid; k < NBOX * 3; k += SELTHR)
        ssup[k] = __ldcg(gsup + k);

    if (tid < NWORDS) {
        unsigned int w = 0;
        for (int jj = 0; jj < 32; jj++) {
            int j = tid * 32 + jj;
            if (j < NBOX && val[j]) w |= (1u << jj);
        }
        keepW[tid] = w;
    }
    __syncthreads();

    // serial greedy pass with early exit after RSEL kept
    if (tid == 0) {
        unsigned int kw[NWORDS];
        #pragma unroll
        for (int q = 0; q < NWORDS; q++) kw[q] = keepW[q];
        int cnt = 0;
        for (int ii = 0; ii < NBOX; ii++) {
            if ((kw[ii >> 5] >> (ii & 31)) & 1u) {
                const uint4 m0 = ssup[ii * 3 + 0];
                const uint4 m1 = ssup[ii * 3 + 1];
                const uint4 m2 = ssup[ii * 3 + 2];
                kw[0] &= ~m0.x; kw[1] &= ~m0.y; kw[2] &= ~m0.z; kw[3] &= ~m0.w;
                kw[4] &= ~m1.x; kw[5] &= ~m1.y; kw[6] &= ~m1.z; kw[7] &= ~m1.w;
                kw[8] &= ~m2.x; kw[9] &= ~m2.y;
                if (++cnt == RSEL) break;  // later boxes all land at pos >= RSEL
            }
        }
        #pragma unroll
        for (int q = 0; q < NWORDS; q++) keepW[q] = kw[q];
    }
    __syncthreads();

    // stable partition select (boxes still shared-resident)
    if (tid < NBOX) {
        const int w = tid >> 5, bit = tid & 31;
        int kept_before = 0;
        for (int q = 0; q < w; q++) kept_before += __popc(keepW[q]);
        kept_before += __popc(keepW[w] & ((1u << bit) - 1u));
        const bool mykeep = (keepW[w] >> bit) & 1u;
        int totKept = 0;
        for (int q = 0; q < NWORDS; q++) totKept += __popc(keepW[q]);

        int pos = mykeep ? kept_before : (totKept + (tid - kept_before));
        if (pos < RSEL) {
            float4 bb = bx[tid];
            sselBox[pos]   = bb;
            sselValid[pos] = mykeep ? 1 : 0;
            float dx = __fsub_rn(bb.z, bb.x), dy = __fsub_rn(bb.w, bb.y);
            float ss = __fadd_rn(__fmul_rn(dx, dx), __fmul_rn(dy, dy));
            float size = sqrtf(fmaxf(ss, 1e-12f));
            float tt = floorf(__fadd_rn(4.0f, log2f(__fmul_rn(__fdiv_rn(size, 224.0f), 4.0f))));
            tt = fminf(fmaxf(tt, 2.0f), 5.0f);
            sselLv[pos] = (int)tt - 2;
        }
    }
    __syncthreads();

    // fused per-ROI pooling plan
    if (tid < RSEL) {
        const int r   = tid;
        const int roi = b * RSEL + r;

        float wx[MAXSPAN];
        #pragma unroll
        for (int q = 0; q < MAXSPAN; q++) wx[q] = 0.0f;

        int Kr = 0, xmin = 0, xmax = -1;
        const int lv = sselLv[r];
        int   rows[MAXROWS];
        float rwt[MAXROWS];

        if (sselValid[r]) {
            const int Hs[4] = {200, 100, 50, 25};
            const int H = Hs[lv], W = H;
            const float4 bb = sselBox[r];
            const float rw = fmaxf(__fsub_rn(bb.z, bb.x), 1.0f);
            const float rh = fmaxf(__fsub_rn(bb.w, bb.y), 1.0f);

            int xm = 0x7fffffff, xM = -1;
            int ix0s[GRIDP], ix1s[GRIDP];
            float lxs[GRIDP], mxs[GRIDP];
            for (int k = 0; k < GRIDP; k++) {
                float g = (k + 0.5f) / (float)GRIDP;
                float X = __fadd_rn(bb.x, __fmul_rn(rw, g));
                float mx = (X < -1.0f || X > (float)W) ? 0.0f : 1.0f;
                float x = fminf(fmaxf(X, 0.0f), (float)(W - 1));
                int i0 = (int)floorf(x);
                int i1 = min(i0 + 1, W - 1);
                ix0s[k] = i0; ix1s[k] = i1;
                lxs[k] = __fsub_rn(x, (float)i0); mxs[k] = mx;
                if (mx > 0.0f) { if (i0 < xm) xm = i0; if (i1 > xM) xM = i1; }
            }
            if (xM >= xm && (xM - xm) < MAXSPAN) {
                for (int k = 0; k < GRIDP; k++) {
                    if (mxs[k] == 0.0f) continue;
                    wx[ix0s[k] - xm] += __fmul_rn(1.0f - lxs[k], mxs[k]);
                    wx[ix1s[k] - xm] += __fmul_rn(lxs[k], mxs[k]);
                }
                xmin = xm; xmax = xM;

                for (int k = 0; k < GRIDP; k++) {
                    float g = (k + 0.5f) / (float)GRIDP;
                    float Y = __fadd_rn(bb.y, __fmul_rn(rh, g));
                    float my = (Y < -1.0f || Y > (float)H) ? 0.0f : 1.0f;
                    float y = fminf(fmaxf(Y, 0.0f), (float)(H - 1));
                    int iy0 = (int)floorf(y);
                    int iy1 = min(iy0 + 1, H - 1);
                    float ly = __fsub_rn(y, (float)iy0);
                    float w0 = __fmul_rn(1.0f - ly, my);
                    float w1 = __fmul_rn(ly, my);
                    for (int tt = 0; tt < 2; tt++) {
                        int   row = tt ? iy1 : iy0;
                        float wv  = tt ? w1 : w0;
                        if (wv == 0.0f) continue;
                        int found = -1;
                        for (int q = 0; q < Kr; q++)
                            if (rows[q] == row) { found = q; break; }
                        if (found >= 0) rwt[found] += wv;
                        else if (Kr < MAXROWS) { rows[Kr] = row; rwt[Kr] = wv; Kr++; }
                    }
                }
            }
        }

        for (int q = 0; q < MAXSPAN; q++) g_wx[roi][q] = wx[q];
        for (int q = 0; q < MAXROWS; q++) {
            g_rows[roi][q] = (q < Kr) ? rows[q] : 0;
            g_rwt[roi][q]  = (q < Kr) ? rwt[q]  : 0.0f;
        }
        g_meta[roi] = make_int4(Kr, xmin, xmax, lv);
    }
}

// ---------------------------------------------------------------------------
// Kernel B: pooling. One warp per (roi, channel). grid (RSEL, BB, 32).
// (exact R5 configuration — 22.7us)
// ---------------------------------------------------------------------------
__global__ void __launch_bounds__(256)
pool_kernel(const float* __restrict__ f0,
            const float* __restrict__ f1,
            const float* __restrict__ f2,
            const float* __restrict__ f3,
            float* __restrict__ out)
{
    const int r = blockIdx.x, b = blockIdx.y;
    const int roi = b * RSEL + r;
    const int tid = threadIdx.x;
    const int warp = tid >> 5, lane = tid & 31;

    __shared__ float swx[MAXSPAN];
    __shared__ int   srows[MAXROWS];
    __shared__ float srwt[MAXROWS];
    __shared__ int4  smeta;

    if (tid < MAXSPAN)                          swx[tid] = g_wx[roi][tid];
    else if (tid < MAXSPAN + MAXROWS)           srows[tid - MAXSPAN] = g_rows[roi][tid - MAXSPAN];
    else if (tid < MAXSPAN + 2 * MAXROWS)       srwt[tid - MAXSPAN - MAXROWS] = g_rwt[roi][tid - MAXSPAN - MAXROWS];
    else if (tid == MAXSPAN + 2 * MAXROWS)      smeta = g_meta[roi];
    __syncthreads();

    const int Kr   = smeta.x;
    const int xmin = smeta.y;
    const int xmax = smeta.z;
    const int lv   = smeta.w;

    const int Hs[4] = {200, 100, 50, 25};
    const int H = Hs[lv], W = H;
    const float* fbase =
        (lv == 0 ? f0 : lv == 1 ? f1 : lv == 2 ? f2 : f3) + (size_t)b * CCH * H * W;

    const int c = blockIdx.z * 8 + warp;
    const float* cp = fbase + (size_t)c * H * W;

    const int x0 = xmin + lane;
    const int x1 = x0 + 32;
    const bool a0 = (x0 <= xmax);
    const bool a1 = (x1 <= xmax);
    const float w0 = a0 ? swx[lane] : 0.0f;
    const float w1 = a1 ? swx[lane + 32] : 0.0f;

    float acc = 0.0f;
    #pragma unroll 4
    for (int j = 0; j < Kr; j++) {
        const float* rp = cp + srows[j] * W;
        float s = 0.0f;
        if (a0) s = rp[x0] * w0;
        if (a1) s += rp[x1] * w1;
        acc += srwt[j] * s;
    }

    #pragma unroll
    for (int o = 16; o > 0; o >>= 1)
        acc += __shfl_xor_sync(0xffffffffu, acc, o);

    if (lane == 0)
        out[(size_t)roi * CCH + c] = acc * (1.0f / 196.0f);
}

// ---------------------------------------------------------------------------
extern "C" void kernel_launch(void* const* d_in, const int* in_sizes, int n_in,
                              void* d_out, int out_size)
{
    const float* boxes  = (const float*)d_in[0];
    const float* scores = (const float*)d_in[1];
    const float* f0     = (const float*)d_in[2];
    const float* f1     = (const float*)d_in[3];
    const float* f2     = (const float*)d_in[4];
    const float* f3     = (const float*)d_in[5];
    float* out = (float*)d_out;

    select_kernel<<<dim3(NWORDS, BB), SELTHR>>>(boxes, scores);
    pool_kernel<<<dim3(RSEL, BB, 32), 256>>>(f0, f1, f2, f3, out);
}